// round 5
// baseline (speedup 1.0000x reference)
#include <cuda_runtime.h>
#include <math.h>

#define NCLS   20
#define GRIDW  38
#define NCELL  1444          // 38*38
#define NANC   5
#define NBOX   16
#define BATCH  64
#define CSTRIDE 180500       // 125 * 1444 floats per batch
#define EPS16  0.0009765625f // 2^-10
#define NBLOCKS 444          // 148 SMs * 3
#define DENSE_BLK0 64
#define NDENSE (NBLOCKS - DENSE_BLK0)

__constant__ float c_anc[NANC][2] = {
    {0.05f, 0.07f}, {0.12f, 0.15f}, {0.25f, 0.30f}, {0.45f, 0.55f}, {0.75f, 0.80f}
};

// 0=S_conf_pos 1=S_neg_marked 2=S_cls 3=S_txty 4=S_twth
// 5=S_neg_all  6=sum 1/nums_pos_b  7=sum 1/nums_neg_b
__device__ float    g_acc[8];   // zeroed at load; finalize re-zeros each replay
__device__ int      g_npos;
__device__ unsigned g_cnt;

__device__ __forceinline__ float htanh(float x) {
    float t;
    asm("tanh.approx.f32 %0, %1;" : "=f"(t) : "f"(x));
    return t;
}

__device__ __forceinline__ float sigmoid_clip(float x) {
    float t = htanh(0.5f * x);
    float p = 0.5f + 0.5f * t;
    return fminf(fmaxf(p, EPS16), 1.0f - EPS16);
}

// -0.5 * p^2 * log(1-p), p = clip(sigmoid(x)); 2 MUFU (tanh + lg2)
__device__ __forceinline__ float fneg(float x) {
    float t = htanh(0.5f * x);
    float p = fminf(fmaxf(0.5f + 0.5f * t, EPS16), 1.0f - EPS16);
    float q = fminf(fmaxf(0.5f - 0.5f * t, EPS16), 1.0f - EPS16);
    return -0.5f * p * p * __logf(q);
}

// release-ordered ticket: orders this thread's prior global atomics before the
// bump; acquire orders the finalizer's subsequent g_acc reads. Replaces
// __threadfence() executed by every thread of every block.
__device__ __forceinline__ unsigned ticket_acq_rel(unsigned* p) {
    unsigned v, one = 1u;
    asm volatile("atom.acq_rel.gpu.add.u32 %0, [%1], %2;"
                 : "=r"(v) : "l"(p), "r"(one) : "memory");
    return v;
}

__global__ void __launch_bounds__(256)
k_fused(const float* __restrict__ py,
        const float* __restrict__ gb,
        const int*   __restrict__ gl,
        float* __restrict__ out) {
    // ---------------- sparse blocks 0..63: matching + positive terms ----------------
    if (blockIdx.x < DENSE_BLK0) {
        if (threadIdx.x < 32) {
            const int b    = blockIdx.x;
            const int lane = threadIdx.x;

            __shared__ int   s_cell[NBOX], s_anc[NBOX];
            __shared__ float s_tx[NBOX], s_ty[NBOX], s_twx[NBOX], s_twy[NBOX], s_wpos[NBOX];
            int my_key = -1, my_lab = 0;

            if (lane < NBOX) {
                const float* bp = gb + (b * NBOX + lane) * 4;
                float4 bx = *reinterpret_cast<const float4*>(bp);
                int labv = gl[b * NBOX + lane];
                float l = bx.x, t = bx.y, r = bx.z, d = bx.w;
                float cx = (l + r) * 0.5f, cy = (t + d) * 0.5f;
                float w  = r - l,          h  = d - t;

                int bi = 0; float best = -1.0f;
                #pragma unroll
                for (int a = 0; a < NANC; a++) {
                    float aw = c_anc[a][0], ah = c_anc[a][1];
                    float inter = fminf(w, aw) * fminf(h, ah);
                    float un    = w * h + aw * ah - inter;
                    float iou   = inter / un;
                    if (iou > best) { best = iou; bi = a; }
                }
                int col = (int)floorf(cx * GRIDW); col = min(max(col, 0), GRIDW - 1);
                int row = (int)floorf(cy * GRIDW); row = min(max(row, 0), GRIDW - 1);
                int cell = row * GRIDW + col;

                s_cell[lane] = cell;
                s_anc[lane]  = bi;
                my_key       = cell * NANC + bi;
                my_lab       = labv - 1;
                s_tx[lane]   = cx * GRIDW - (float)col;
                s_ty[lane]   = cy * GRIDW - (float)row;
                s_twx[lane]  = __logf(w / c_anc[bi][0]);
                s_twy[lane]  = __logf(h / c_anc[bi][1]);
                s_wpos[lane] = l;  // replicates reference index bug: gy[...,26] = left coord
            }
            __syncwarp();

            int live = 0, first = 0;
            if (lane < NBOX) {
                live = 1;
                for (int j = lane + 1; j < NBOX; j++)
                    if (s_cell[j] * NANC + s_anc[j] == my_key) { live = 0; break; }
                first = 1;
                for (int j = 0; j < lane; j++)
                    if (s_cell[j] == s_cell[lane]) { first = 0; break; }
            }
            unsigned mlive  = __ballot_sync(0xffffffffu, live);
            unsigned mfirst = __ballot_sync(0xffffffffu, first);
            int npos   = __popc(mlive);
            int ncellm = __popc(mfirst);
            float nneg = (float)(NANC * NCELL - NANC * ncellm);

            float a_conf = 0.f, a_cls = 0.f, a_txy = 0.f, a_twh = 0.f, a_sub = 0.f;
            const float* base = py + (long long)b * CSTRIDE;

            // batch ALL positive gathers (25 loads) before consuming: one DRAM round
            if (lane < NBOX && live) {
                int cell = s_cell[lane], anc = s_anc[lane], lab = my_lab;
                int o = anc * NCELL + cell;

                float xconf = __ldg(base + o);
                float xc[NCLS];
                #pragma unroll
                for (int f = 0; f < NCLS; f++)
                    xc[f] = __ldg(base + o + (f + 1) * (NANC * NCELL));
                float xtx = __ldg(base + o + 21 * (NANC * NCELL));
                float xty = __ldg(base + o + 22 * (NANC * NCELL));
                float xwx = __ldg(base + o + 23 * (NANC * NCELL));
                float xwy = __ldg(base + o + 24 * (NANC * NCELL));

                float p = sigmoid_clip(xconf);
                float om = 1.0f - p;
                a_conf = -0.5f * om * om * __logf(p);

                #pragma unroll
                for (int f = 0; f < NCLS; f++) {
                    float pc = sigmoid_clip(xc[f]);
                    float g  = (f == lab) ? 1.0f : 0.0f;
                    a_cls += -(g * __logf(pc) + (1.0f - g) * __logf(1.0f - pc));
                }

                float wpos = s_wpos[lane];
                float ptx = sigmoid_clip(xtx);
                float pty = sigmoid_clip(xty);
                float gx = s_tx[lane], gy = s_ty[lane];
                float bcex = -(gx * __logf(ptx) + (1.0f - gx) * __logf(1.0f - ptx));
                float bcey = -(gy * __logf(pty) + (1.0f - gy) * __logf(1.0f - pty));
                a_txy = (bcex + bcey) * wpos;

                float dx = xwx - s_twx[lane];
                float dy = xwy - s_twy[lane];
                a_twh = (dx * dx + dy * dy) * wpos;
            }

            // marked-cell anchors: 3 independent gated loads per lane, batched
            {
                float xs[3]; int have[3];
                #pragma unroll
                for (int it = 0; it < 3; it++) {
                    int k = lane + it * 32;
                    int i = k / NANC, a = k - i * NANC;
                    have[it] = (k < NBOX * NANC) && ((mfirst >> i) & 1u);
                    if (have[it]) xs[it] = __ldg(base + a * NCELL + s_cell[i]);
                }
                #pragma unroll
                for (int it = 0; it < 3; it++)
                    if (have[it]) a_sub += fneg(xs[it]);
            }

            #pragma unroll
            for (int off = 16; off; off >>= 1) {
                a_conf += __shfl_down_sync(0xffffffffu, a_conf, off);
                a_cls  += __shfl_down_sync(0xffffffffu, a_cls,  off);
                a_txy  += __shfl_down_sync(0xffffffffu, a_txy,  off);
                a_twh  += __shfl_down_sync(0xffffffffu, a_twh,  off);
                a_sub  += __shfl_down_sync(0xffffffffu, a_sub,  off);
            }
            if (lane == 0) {
                atomicAdd(&g_acc[0], a_conf);
                atomicAdd(&g_acc[1], a_sub);
                atomicAdd(&g_acc[2], a_cls);
                atomicAdd(&g_acc[3], a_txy);
                atomicAdd(&g_acc[4], a_twh);
                atomicAdd(&g_acc[6], 1.0f / fmaxf((float)npos, EPS16));
                atomicAdd(&g_acc[7], 1.0f / fmaxf(nneg, EPS16));
                atomicAdd(&g_npos, npos);
            }
        }
    }
    // ---------------- dense blocks 64..443: conf-neg sum ----------------
    else {
        const int TOT4   = BATCH * NANC * NCELL / 4;  // 115520
        const int PER_B4 = NANC * NCELL / 4;          // 1805
        const int CS4    = CSTRIDE / 4;               // 45125
        const int STRIDE = NDENSE * 256;              // 97280
        const float4* p4 = reinterpret_cast<const float4*>(py);

        const int q0 = (blockIdx.x - DENSE_BLK0) * 256 + threadIdx.x;
        const int q1 = q0 + STRIDE;

        float4 v0, v1;
        bool has1 = (q1 < TOT4);
        {
            int b = q0 / PER_B4, r = q0 - b * PER_B4;
            v0 = p4[(long long)b * CS4 + r];
        }
        if (has1) {
            int b = q1 / PER_B4, r = q1 - b * PER_B4;
            v1 = p4[(long long)b * CS4 + r];
        }

        float acc = fneg(v0.x) + fneg(v0.y) + fneg(v0.z) + fneg(v0.w);
        if (has1)
            acc += fneg(v1.x) + fneg(v1.y) + fneg(v1.z) + fneg(v1.w);

        __shared__ float sh[8];
        float s = acc;
        #pragma unroll
        for (int off = 16; off; off >>= 1) s += __shfl_down_sync(0xffffffffu, s, off);
        int w = threadIdx.x >> 5, l = threadIdx.x & 31;
        if (l == 0) sh[w] = s;
        __syncthreads();
        if (w == 0) {
            s = (l < 8) ? sh[l] : 0.0f;
            #pragma unroll
            for (int off = 4; off; off >>= 1) s += __shfl_down_sync(0xffffffffu, s, off);
            if (l == 0) atomicAdd(&g_acc[5], s);
        }
    }

    // ---------------- finalize: thread 0 only, release/acquire ticket ----------------
    if (threadIdx.x == 0) {
        unsigned v = ticket_acq_rel(&g_cnt);
        if (v == NBLOCKS - 1) {
            float npos_tot = fmaxf((float)g_npos, 1.0f);
            float sneg = g_acc[5] - g_acc[1];
            float loss = g_acc[0] * (g_acc[6] * (1.0f / BATCH))
                       + 3.0f * sneg * (g_acc[7] * (1.0f / BATCH))
                       + (g_acc[2] + g_acc[3] + g_acc[4]) / npos_tot;
            out[0] = loss;
            #pragma unroll
            for (int i = 0; i < 8; i++) g_acc[i] = 0.0f;
            g_npos = 0;
            g_cnt  = 0;
        }
    }
}

extern "C" void kernel_launch(void* const* d_in, const int* in_sizes, int n_in,
                              void* d_out, int out_size) {
    const float* py = (const float*)d_in[0];
    const float* gb = (const float*)d_in[1];
    const int*   gl = (const int*)d_in[2];
    float* out = (float*)d_out;

    k_fused<<<NBLOCKS, 256>>>(py, gb, gl, out);
}

// round 6
// speedup vs baseline: 1.0238x; 1.0238x over previous
#include <cuda_runtime.h>
#include <math.h>

#define NCLS   20
#define GRIDW  38
#define NCELL  1444          // 38*38
#define NANC   5
#define NBOX   16
#define BATCH  64
#define CSTRIDE 180500       // 125 * 1444 floats per batch
#define EPS16  0.0009765625f // 2^-10
#define NBLOCKS 148          // 1 CTA per SM, 1024 threads
#define NTHREADS 1024
#define TOT4   (BATCH * NANC * NCELL / 4)   // 115520 float4 conf elements
#define PER_B4 (NANC * NCELL / 4)           // 1805
#define CS4    (CSTRIDE / 4)                // 45125
#define NTICKETS (NBLOCKS + BATCH)          // 148 block bumps + 64 sparse-warp bumps

__constant__ float c_anc[NANC][2] = {
    {0.05f, 0.07f}, {0.12f, 0.15f}, {0.25f, 0.30f}, {0.45f, 0.55f}, {0.75f, 0.80f}
};

// 0=S_conf_pos 1=S_neg_marked 2=S_cls 3=S_txty 4=S_twth
// 5=S_neg_all  6=sum 1/nums_pos_b  7=sum 1/nums_neg_b
__device__ float    g_acc[8];   // zeroed at load; finalize re-zeros each replay
__device__ int      g_npos;
__device__ unsigned g_cnt;

__device__ __forceinline__ float htanh(float x) {
    float t;
    asm("tanh.approx.f32 %0, %1;" : "=f"(t) : "f"(x));
    return t;
}

__device__ __forceinline__ float sigmoid_clip(float x) {
    float t = htanh(0.5f * x);
    float p = 0.5f + 0.5f * t;
    return fminf(fmaxf(p, EPS16), 1.0f - EPS16);
}

// -0.5 * p^2 * log(1-p), p = clip(sigmoid(x)); 2 MUFU (tanh + lg2)
__device__ __forceinline__ float fneg(float x) {
    float t = htanh(0.5f * x);
    float p = fminf(fmaxf(0.5f + 0.5f * t, EPS16), 1.0f - EPS16);
    float q = fminf(fmaxf(0.5f - 0.5f * t, EPS16), 1.0f - EPS16);
    return -0.5f * p * p * __logf(q);
}

// acq_rel ticket: release orders this thread's prior atomics before the bump;
// acquire orders the finalizer's g_acc reads after the last bump.
__device__ __forceinline__ unsigned ticket_acq_rel(unsigned* p) {
    unsigned v, one = 1u;
    asm volatile("atom.acq_rel.gpu.add.u32 %0, [%1], %2;"
                 : "=r"(v) : "l"(p), "r"(one) : "memory");
    return v;
}

__device__ __forceinline__ void finalize_and_reset(float* out) {
    float npos_tot = fmaxf((float)g_npos, 1.0f);
    float sneg = g_acc[5] - g_acc[1];
    float loss = g_acc[0] * (g_acc[6] * (1.0f / BATCH))
               + 3.0f * sneg * (g_acc[7] * (1.0f / BATCH))
               + (g_acc[2] + g_acc[3] + g_acc[4]) / npos_tot;
    out[0] = loss;
    #pragma unroll
    for (int i = 0; i < 8; i++) g_acc[i] = 0.0f;
    g_npos = 0;
    g_cnt  = 0;
}

__global__ void __launch_bounds__(NTHREADS, 1)
k_fused(const float* __restrict__ py,
        const float* __restrict__ gb,
        const int*   __restrict__ gl,
        float* __restrict__ out) {
    const int bid = blockIdx.x;
    const int tid = threadIdx.x;
    const int wid = tid >> 5;
    const bool is_sparse_warp = (bid < BATCH) && (wid == 31);

    __shared__ float sh[32];

    // ---------------- dense: one float4 per thread ----------------
    float acc = 0.0f;
    if (!is_sparse_warp) {
        // blocks 0..63 have 992 dense threads (warps 0-30); blocks 64..147 have 1024
        int q = (bid < BATCH) ? (bid * 992 + tid)
                              : (BATCH * 992 + (bid - BATCH) * NTHREADS + tid);
        if (q < TOT4) {
            int b = q / PER_B4, r = q - b * PER_B4;
            float4 v = reinterpret_cast<const float4*>(py)[(long long)b * CS4 + r];
            acc = fneg(v.x) + fneg(v.y) + fneg(v.z) + fneg(v.w);
        }
    }

    // ---------------- sparse: warp 31 of blocks 0..63 ----------------
    if (is_sparse_warp) {
        const int b    = bid;
        const int lane = tid & 31;

        __shared__ int   s_cell[NBOX], s_anc[NBOX];
        __shared__ float s_tx[NBOX], s_ty[NBOX], s_twx[NBOX], s_twy[NBOX], s_wpos[NBOX];
        int my_key = -1, my_lab = 0;

        if (lane < NBOX) {
            const float* bp = gb + (b * NBOX + lane) * 4;
            float4 bx = *reinterpret_cast<const float4*>(bp);
            int labv = gl[b * NBOX + lane];
            float l = bx.x, t = bx.y, r = bx.z, d = bx.w;
            float cx = (l + r) * 0.5f, cy = (t + d) * 0.5f;
            float w  = r - l,          h  = d - t;

            int bi = 0; float best = -1.0f;
            #pragma unroll
            for (int a = 0; a < NANC; a++) {
                float aw = c_anc[a][0], ah = c_anc[a][1];
                float inter = fminf(w, aw) * fminf(h, ah);
                float un    = w * h + aw * ah - inter;
                float iou   = inter / un;
                if (iou > best) { best = iou; bi = a; }
            }
            int col = (int)floorf(cx * GRIDW); col = min(max(col, 0), GRIDW - 1);
            int row = (int)floorf(cy * GRIDW); row = min(max(row, 0), GRIDW - 1);
            int cell = row * GRIDW + col;

            s_cell[lane] = cell;
            s_anc[lane]  = bi;
            my_key       = cell * NANC + bi;
            my_lab       = labv - 1;
            s_tx[lane]   = cx * GRIDW - (float)col;
            s_ty[lane]   = cy * GRIDW - (float)row;
            s_twx[lane]  = __logf(w / c_anc[bi][0]);
            s_twy[lane]  = __logf(h / c_anc[bi][1]);
            s_wpos[lane] = l;  // replicates reference index bug: gy[...,26] = left coord
        }
        __syncwarp();

        int live = 0, first = 0;
        if (lane < NBOX) {
            live = 1;
            for (int j = lane + 1; j < NBOX; j++)
                if (s_cell[j] * NANC + s_anc[j] == my_key) { live = 0; break; }
            first = 1;
            for (int j = 0; j < lane; j++)
                if (s_cell[j] == s_cell[lane]) { first = 0; break; }
        }
        unsigned mlive  = __ballot_sync(0xffffffffu, live);
        unsigned mfirst = __ballot_sync(0xffffffffu, first);
        int npos   = __popc(mlive);
        int ncellm = __popc(mfirst);
        float nneg = (float)(NANC * NCELL - NANC * ncellm);

        float a_conf = 0.f, a_cls = 0.f, a_txy = 0.f, a_twh = 0.f, a_sub = 0.f;
        const float* base = py + (long long)b * CSTRIDE;

        // batch ALL positive gathers (25 loads) before consuming: one memory round
        if (lane < NBOX && live) {
            int cell = s_cell[lane], anc = s_anc[lane], lab = my_lab;
            int o = anc * NCELL + cell;

            float xconf = __ldg(base + o);
            float xc[NCLS];
            #pragma unroll
            for (int f = 0; f < NCLS; f++)
                xc[f] = __ldg(base + o + (f + 1) * (NANC * NCELL));
            float xtx = __ldg(base + o + 21 * (NANC * NCELL));
            float xty = __ldg(base + o + 22 * (NANC * NCELL));
            float xwx = __ldg(base + o + 23 * (NANC * NCELL));
            float xwy = __ldg(base + o + 24 * (NANC * NCELL));

            float p = sigmoid_clip(xconf);
            float om = 1.0f - p;
            a_conf = -0.5f * om * om * __logf(p);

            #pragma unroll
            for (int f = 0; f < NCLS; f++) {
                float pc = sigmoid_clip(xc[f]);
                float g  = (f == lab) ? 1.0f : 0.0f;
                a_cls += -(g * __logf(pc) + (1.0f - g) * __logf(1.0f - pc));
            }

            float wpos = s_wpos[lane];
            float ptx = sigmoid_clip(xtx);
            float pty = sigmoid_clip(xty);
            float gx = s_tx[lane], gy = s_ty[lane];
            float bcex = -(gx * __logf(ptx) + (1.0f - gx) * __logf(1.0f - ptx));
            float bcey = -(gy * __logf(pty) + (1.0f - gy) * __logf(1.0f - pty));
            a_txy = (bcex + bcey) * wpos;

            float dx = xwx - s_twx[lane];
            float dy = xwy - s_twy[lane];
            a_twh = (dx * dx + dy * dy) * wpos;
        }

        // marked-cell anchors: 3 independent gated loads per lane, batched
        {
            float xs[3]; int have[3];
            #pragma unroll
            for (int it = 0; it < 3; it++) {
                int k = lane + it * 32;
                int i = k / NANC, a = k - i * NANC;
                have[it] = (k < NBOX * NANC) && ((mfirst >> i) & 1u);
                if (have[it]) xs[it] = __ldg(base + a * NCELL + s_cell[i]);
            }
            #pragma unroll
            for (int it = 0; it < 3; it++)
                if (have[it]) a_sub += fneg(xs[it]);
        }

        #pragma unroll
        for (int off = 16; off; off >>= 1) {
            a_conf += __shfl_down_sync(0xffffffffu, a_conf, off);
            a_cls  += __shfl_down_sync(0xffffffffu, a_cls,  off);
            a_txy  += __shfl_down_sync(0xffffffffu, a_txy,  off);
            a_twh  += __shfl_down_sync(0xffffffffu, a_twh,  off);
            a_sub  += __shfl_down_sync(0xffffffffu, a_sub,  off);
        }
        if (lane == 0) {
            atomicAdd(&g_acc[0], a_conf);
            atomicAdd(&g_acc[1], a_sub);
            atomicAdd(&g_acc[2], a_cls);
            atomicAdd(&g_acc[3], a_txy);
            atomicAdd(&g_acc[4], a_twh);
            atomicAdd(&g_acc[6], 1.0f / fmaxf((float)npos, EPS16));
            atomicAdd(&g_acc[7], 1.0f / fmaxf(nneg, EPS16));
            atomicAdd(&g_npos, npos);
            // sparse-warp ticket (release): covers the 8 atomics above
            unsigned v = ticket_acq_rel(&g_cnt);
            if (v == NTICKETS - 1) finalize_and_reset(out);
        }
    }

    // ---------------- block reduction of dense partials ----------------
    {
        float s = acc;
        #pragma unroll
        for (int off = 16; off; off >>= 1) s += __shfl_down_sync(0xffffffffu, s, off);
        int l = tid & 31;
        if (l == 0) sh[wid] = s;
        __syncthreads();
        if (wid == 0) {
            s = sh[l];
            #pragma unroll
            for (int off = 16; off; off >>= 1) s += __shfl_down_sync(0xffffffffu, s, off);
            if (l == 0) {
                atomicAdd(&g_acc[5], s);
                unsigned v = ticket_acq_rel(&g_cnt);
                if (v == NTICKETS - 1) finalize_and_reset(out);
            }
        }
    }
}

extern "C" void kernel_launch(void* const* d_in, const int* in_sizes, int n_in,
                              void* d_out, int out_size) {
    const float* py = (const float*)d_in[0];
    const float* gb = (const float*)d_in[1];
    const int*   gl = (const int*)d_in[2];
    float* out = (float*)d_out;

    k_fused<<<NBLOCKS, NTHREADS>>>(py, gb, gl, out);
}

// round 7
// speedup vs baseline: 1.0269x; 1.0030x over previous
#include <cuda_runtime.h>
#include <math.h>

#define NCLS   20
#define GRIDW  38
#define NCELL  1444          // 38*38
#define NANC   5
#define NBOX   16
#define BATCH  64
#define CSTRIDE 180500       // 125 * 1444 floats per batch
#define EPS16  0.0009765625f // 2^-10
#define NBLOCKS 148
#define NTHREADS 256
#define TOT4   (BATCH * NANC * NCELL / 4)   // 115520 float4 conf elements
#define PER_B4 (NANC * NCELL / 4)           // 1805
#define CS4    (CSTRIDE / 4)                // 45125
#define NDT    (64 * 224 + 84 * 256)        // 35840 dense threads
#define REM    (TOT4 - 3 * NDT)             // 8000 threads take a 4th element
#define NTICKETS (NBLOCKS + BATCH)          // 148 block bumps + 64 sparse-warp bumps

__constant__ float c_anc[NANC][2] = {
    {0.05f, 0.07f}, {0.12f, 0.15f}, {0.25f, 0.30f}, {0.45f, 0.55f}, {0.75f, 0.80f}
};

// 0=S_conf_pos 1=S_neg_marked 2=S_cls 3=S_txty 4=S_twth
// 5=S_neg_all  6=sum 1/nums_pos_b  7=sum 1/nums_neg_b
__device__ float    g_acc[8];   // zeroed at load; finalize re-zeros each replay
__device__ int      g_npos;
__device__ unsigned g_cnt;

__device__ __forceinline__ float htanh(float x) {
    float t;
    asm("tanh.approx.f32 %0, %1;" : "=f"(t) : "f"(x));
    return t;
}

__device__ __forceinline__ float sigmoid_clip(float x) {
    float t = htanh(0.5f * x);
    float p = 0.5f + 0.5f * t;
    return fminf(fmaxf(p, EPS16), 1.0f - EPS16);
}

// -0.5 * p^2 * log(1-p), p = clip(sigmoid(x)); 2 MUFU (tanh + lg2)
__device__ __forceinline__ float fneg(float x) {
    float t = htanh(0.5f * x);
    float p = fminf(fmaxf(0.5f + 0.5f * t, EPS16), 1.0f - EPS16);
    float q = fminf(fmaxf(0.5f - 0.5f * t, EPS16), 1.0f - EPS16);
    return -0.5f * p * p * __logf(q);
}

__device__ __forceinline__ unsigned ticket_acq_rel(unsigned* p) {
    unsigned v, one = 1u;
    asm volatile("atom.acq_rel.gpu.add.u32 %0, [%1], %2;"
                 : "=r"(v) : "l"(p), "r"(one) : "memory");
    return v;
}

__device__ __forceinline__ void finalize_and_reset(float* out) {
    float npos_tot = fmaxf((float)g_npos, 1.0f);
    float sneg = g_acc[5] - g_acc[1];
    float loss = g_acc[0] * (g_acc[6] * (1.0f / BATCH))
               + 3.0f * sneg * (g_acc[7] * (1.0f / BATCH))
               + (g_acc[2] + g_acc[3] + g_acc[4]) / npos_tot;
    out[0] = loss;
    #pragma unroll
    for (int i = 0; i < 8; i++) g_acc[i] = 0.0f;
    g_npos = 0;
    g_cnt  = 0;
}

__device__ __forceinline__ float4 ld4(const float4* p4, int q) {
    int b = q / PER_B4, r = q - b * PER_B4;
    return p4[b * CS4 + r];
}

__global__ void __launch_bounds__(NTHREADS, 1)
k_fused(const float* __restrict__ py,
        const float* __restrict__ gb,
        const int*   __restrict__ gl,
        float* __restrict__ out) {
    const int bid = blockIdx.x;
    const int tid = threadIdx.x;
    const int wid = tid >> 5;
    const bool is_sparse_warp = (bid < BATCH) && (wid == 7);

    __shared__ float sh[8];

    // ---------------- dense: 3-4 float4 per thread, all loads batched ----------------
    float acc = 0.0f;
    if (!is_sparse_warp) {
        int dt = (bid < BATCH) ? (bid * 224 + tid)
                               : (64 * 224 + (bid - BATCH) * NTHREADS + tid);
        const float4* p4 = reinterpret_cast<const float4*>(py);
        bool h3 = (dt < REM);
        float4 v0 = ld4(p4, dt);
        float4 v1 = ld4(p4, dt + NDT);
        float4 v2 = ld4(p4, dt + 2 * NDT);
        float4 v3;
        if (h3) v3 = ld4(p4, dt + 3 * NDT);

        acc  = fneg(v0.x) + fneg(v0.y) + fneg(v0.z) + fneg(v0.w);
        acc += fneg(v1.x) + fneg(v1.y) + fneg(v1.z) + fneg(v1.w);
        acc += fneg(v2.x) + fneg(v2.y) + fneg(v2.z) + fneg(v2.w);
        if (h3) acc += fneg(v3.x) + fneg(v3.y) + fneg(v3.z) + fneg(v3.w);
    }

    // ---------------- sparse: warp 7 of blocks 0..63 ----------------
    if (is_sparse_warp) {
        const int b    = bid;
        const int lane = tid & 31;

        __shared__ int   s_cell[NBOX], s_anc[NBOX];
        __shared__ float s_tx[NBOX], s_ty[NBOX], s_twx[NBOX], s_twy[NBOX], s_wpos[NBOX];
        int my_key = -1, my_lab = 0;

        if (lane < NBOX) {
            const float* bp = gb + (b * NBOX + lane) * 4;
            float4 bx = *reinterpret_cast<const float4*>(bp);
            int labv = gl[b * NBOX + lane];
            float l = bx.x, t = bx.y, r = bx.z, d = bx.w;
            float cx = (l + r) * 0.5f, cy = (t + d) * 0.5f;
            float w  = r - l,          h  = d - t;

            int bi = 0; float best = -1.0f;
            #pragma unroll
            for (int a = 0; a < NANC; a++) {
                float aw = c_anc[a][0], ah = c_anc[a][1];
                float inter = fminf(w, aw) * fminf(h, ah);
                float un    = w * h + aw * ah - inter;
                float iou   = inter / un;
                if (iou > best) { best = iou; bi = a; }
            }
            int col = (int)floorf(cx * GRIDW); col = min(max(col, 0), GRIDW - 1);
            int row = (int)floorf(cy * GRIDW); row = min(max(row, 0), GRIDW - 1);
            int cell = row * GRIDW + col;

            s_cell[lane] = cell;
            s_anc[lane]  = bi;
            my_key       = cell * NANC + bi;
            my_lab       = labv - 1;
            s_tx[lane]   = cx * GRIDW - (float)col;
            s_ty[lane]   = cy * GRIDW - (float)row;
            s_twx[lane]  = __logf(w / c_anc[bi][0]);
            s_twy[lane]  = __logf(h / c_anc[bi][1]);
            s_wpos[lane] = l;  // replicates reference index bug: gy[...,26] = left coord
        }
        __syncwarp();

        int live = 0, first = 0;
        if (lane < NBOX) {
            live = 1;
            for (int j = lane + 1; j < NBOX; j++)
                if (s_cell[j] * NANC + s_anc[j] == my_key) { live = 0; break; }
            first = 1;
            for (int j = 0; j < lane; j++)
                if (s_cell[j] == s_cell[lane]) { first = 0; break; }
        }
        unsigned mlive  = __ballot_sync(0xffffffffu, live);
        unsigned mfirst = __ballot_sync(0xffffffffu, first);
        int npos   = __popc(mlive);
        int ncellm = __popc(mfirst);
        float nneg = (float)(NANC * NCELL - NANC * ncellm);

        float a_conf = 0.f, a_cls = 0.f, a_txy = 0.f, a_twh = 0.f, a_sub = 0.f;
        const float* base = py + b * CSTRIDE;

        // batch ALL positive gathers (25 loads) before consuming: one memory round
        if (lane < NBOX && live) {
            int cell = s_cell[lane], anc = s_anc[lane], lab = my_lab;
            int o = anc * NCELL + cell;

            float xconf = __ldg(base + o);
            float xc[NCLS];
            #pragma unroll
            for (int f = 0; f < NCLS; f++)
                xc[f] = __ldg(base + o + (f + 1) * (NANC * NCELL));
            float xtx = __ldg(base + o + 21 * (NANC * NCELL));
            float xty = __ldg(base + o + 22 * (NANC * NCELL));
            float xwx = __ldg(base + o + 23 * (NANC * NCELL));
            float xwy = __ldg(base + o + 24 * (NANC * NCELL));

            float p = sigmoid_clip(xconf);
            float om = 1.0f - p;
            a_conf = -0.5f * om * om * __logf(p);

            #pragma unroll
            for (int f = 0; f < NCLS; f++) {
                float pc = sigmoid_clip(xc[f]);
                float g  = (f == lab) ? 1.0f : 0.0f;
                a_cls += -(g * __logf(pc) + (1.0f - g) * __logf(1.0f - pc));
            }

            float wpos = s_wpos[lane];
            float ptx = sigmoid_clip(xtx);
            float pty = sigmoid_clip(xty);
            float gx = s_tx[lane], gy = s_ty[lane];
            float bcex = -(gx * __logf(ptx) + (1.0f - gx) * __logf(1.0f - ptx));
            float bcey = -(gy * __logf(pty) + (1.0f - gy) * __logf(1.0f - pty));
            a_txy = (bcex + bcey) * wpos;

            float dx = xwx - s_twx[lane];
            float dy = xwy - s_twy[lane];
            a_twh = (dx * dx + dy * dy) * wpos;
        }

        // marked-cell anchors: 3 independent gated loads per lane, batched
        {
            float xs[3]; int have[3];
            #pragma unroll
            for (int it = 0; it < 3; it++) {
                int k = lane + it * 32;
                int i = k / NANC, a = k - i * NANC;
                have[it] = (k < NBOX * NANC) && ((mfirst >> i) & 1u);
                if (have[it]) xs[it] = __ldg(base + a * NCELL + s_cell[i]);
            }
            #pragma unroll
            for (int it = 0; it < 3; it++)
                if (have[it]) a_sub += fneg(xs[it]);
        }

        #pragma unroll
        for (int off = 16; off; off >>= 1) {
            a_conf += __shfl_down_sync(0xffffffffu, a_conf, off);
            a_cls  += __shfl_down_sync(0xffffffffu, a_cls,  off);
            a_txy  += __shfl_down_sync(0xffffffffu, a_txy,  off);
            a_twh  += __shfl_down_sync(0xffffffffu, a_twh,  off);
            a_sub  += __shfl_down_sync(0xffffffffu, a_sub,  off);
        }
        if (lane == 0) {
            atomicAdd(&g_acc[0], a_conf);
            atomicAdd(&g_acc[1], a_sub);
            atomicAdd(&g_acc[2], a_cls);
            atomicAdd(&g_acc[3], a_txy);
            atomicAdd(&g_acc[4], a_twh);
            atomicAdd(&g_acc[6], 1.0f / fmaxf((float)npos, EPS16));
            atomicAdd(&g_acc[7], 1.0f / fmaxf(nneg, EPS16));
            atomicAdd(&g_npos, npos);
            unsigned v = ticket_acq_rel(&g_cnt);  // release: covers 8 atomics above
            if (v == NTICKETS - 1) finalize_and_reset(out);
        }
    }

    // ---------------- block reduction of dense partials ----------------
    {
        float s = acc;
        #pragma unroll
        for (int off = 16; off; off >>= 1) s += __shfl_down_sync(0xffffffffu, s, off);
        int l = tid & 31;
        if (l == 0) sh[wid] = s;
        __syncthreads();
        if (wid == 0) {
            s = (l < 8) ? sh[l] : 0.0f;
            #pragma unroll
            for (int off = 4; off; off >>= 1) s += __shfl_down_sync(0xffffffffu, s, off);
            if (l == 0) {
                atomicAdd(&g_acc[5], s);
                unsigned v = ticket_acq_rel(&g_cnt);
                if (v == NTICKETS - 1) finalize_and_reset(out);
            }
        }
    }
}

extern "C" void kernel_launch(void* const* d_in, const int* in_sizes, int n_in,
                              void* d_out, int out_size) {
    const float* py = (const float*)d_in[0];
    const float* gb = (const float*)d_in[1];
    const int*   gl = (const int*)d_in[2];
    float* out = (float*)d_out;

    k_fused<<<NBLOCKS, NTHREADS>>>(py, gb, gl, out);
}

// round 8
// speedup vs baseline: 1.2694x; 1.2362x over previous
#include <cuda_runtime.h>
#include <math.h>

#define NCLS   20
#define GRIDW  38
#define NCELL  1444          // 38*38
#define NANC   5
#define NBOX   16
#define BATCH  64
#define CSTRIDE 180500       // 125 * 1444 floats per batch
#define EPS16  0.0009765625f // 2^-10
#define NBLOCKS 148
#define NTHREADS 256
#define TOT4   (BATCH * NANC * NCELL / 4)   // 115520 float4 conf elements
#define PER_B4 (NANC * NCELL / 4)           // 1805
#define CS4    (CSTRIDE / 4)                // 45125
#define NDT    (64 * 224 + 84 * 256)        // 35840 dense threads
#define REM    (TOT4 - 3 * NDT)             // first REM threads take a 4th element
#define NTICKETS (NBLOCKS + BATCH)          // 148 block bumps + 64 sparse-warp bumps

__constant__ float c_anc[NANC][2] = {
    {0.05f, 0.07f}, {0.12f, 0.15f}, {0.25f, 0.30f}, {0.45f, 0.55f}, {0.75f, 0.80f}
};

// 0=S_conf_pos 1=S_neg_marked 2=S_cls 3=S_txty 4=S_twth
// 5=S_neg_all  6=sum 1/nums_pos_b  7=sum 1/nums_neg_b
__device__ float    g_acc[8];   // zeroed at load; finalize re-zeros each replay
__device__ int      g_npos;
__device__ unsigned g_cnt;

__device__ __forceinline__ float htanh(float x) {
    float t;
    asm("tanh.approx.f32 %0, %1;" : "=f"(t) : "f"(x));
    return t;
}

__device__ __forceinline__ float sigmoid_clip(float x) {
    float t = htanh(0.5f * x);
    float p = 0.5f + 0.5f * t;
    return fminf(fmaxf(p, EPS16), 1.0f - EPS16);
}

// -0.5 * p^2 * log(1-p), p = clip(sigmoid(x)); 2 MUFU (tanh + lg2)
__device__ __forceinline__ float fneg(float x) {
    float t = htanh(0.5f * x);
    float p = fminf(fmaxf(0.5f + 0.5f * t, EPS16), 1.0f - EPS16);
    float q = fminf(fmaxf(0.5f - 0.5f * t, EPS16), 1.0f - EPS16);
    return -0.5f * p * p * __logf(q);
}

__device__ __forceinline__ unsigned ticket_acq_rel(unsigned* p) {
    unsigned v, one = 1u;
    asm volatile("atom.acq_rel.gpu.add.u32 %0, [%1], %2;"
                 : "=r"(v) : "l"(p), "r"(one) : "memory");
    return v;
}

__device__ __forceinline__ void finalize_and_reset(float* out) {
    float npos_tot = fmaxf((float)g_npos, 1.0f);
    float sneg = g_acc[5] - g_acc[1];
    float loss = g_acc[0] * (g_acc[6] * (1.0f / BATCH))
               + 3.0f * sneg * (g_acc[7] * (1.0f / BATCH))
               + (g_acc[2] + g_acc[3] + g_acc[4]) / npos_tot;
    out[0] = loss;
    #pragma unroll
    for (int i = 0; i < 8; i++) g_acc[i] = 0.0f;
    g_npos = 0;
    g_cnt  = 0;
}

__device__ __forceinline__ float4 ld4(const float4* p4, int q) {
    int b = q / PER_B4, r = q - b * PER_B4;
    return p4[b * CS4 + r];
}

__global__ void __launch_bounds__(NTHREADS, 1)
k_fused(const float* __restrict__ py,
        const float* __restrict__ gb,
        const int*   __restrict__ gl,
        float* __restrict__ out) {
    const int bid = blockIdx.x;
    const int tid = threadIdx.x;
    const int wid = tid >> 5;
    const bool is_sparse_warp = (bid < BATCH) && (wid == 7);

    __shared__ float sh[8];

    // ---------------- dense: 3-4 float4 per thread, all loads batched ----------------
    float acc = 0.0f;
    if (!is_sparse_warp) {
        int dt = (bid < BATCH) ? (bid * 224 + tid)
                               : (64 * 224 + (bid - BATCH) * NTHREADS + tid);
        const float4* p4 = reinterpret_cast<const float4*>(py);
        bool h3 = (dt < REM);
        float4 v0 = ld4(p4, dt);
        float4 v1 = ld4(p4, dt + NDT);
        float4 v2 = ld4(p4, dt + 2 * NDT);
        float4 v3;
        if (h3) v3 = ld4(p4, dt + 3 * NDT);

        acc  = fneg(v0.x) + fneg(v0.y) + fneg(v0.z) + fneg(v0.w);
        acc += fneg(v1.x) + fneg(v1.y) + fneg(v1.z) + fneg(v1.w);
        acc += fneg(v2.x) + fneg(v2.y) + fneg(v2.z) + fneg(v2.w);
        if (h3) acc += fneg(v3.x) + fneg(v3.y) + fneg(v3.z) + fneg(v3.w);

        // ---------------- dense block reduction (sparse warp NOT involved) ----------
        float s = acc;
        #pragma unroll
        for (int off = 16; off; off >>= 1) s += __shfl_down_sync(0xffffffffu, s, off);
        int l = tid & 31;
        if (l == 0) sh[wid] = s;

        if (bid < BATCH) {
            // only the 7 dense warps (224 threads) sync — sparse warp never gates this
            asm volatile("bar.sync 1, 224;" ::: "memory");
            if (wid == 0) {
                s = (l < 7) ? sh[l] : 0.0f;
                #pragma unroll
                for (int off = 4; off; off >>= 1) s += __shfl_down_sync(0xffffffffu, s, off);
                if (l == 0) {
                    atomicAdd(&g_acc[5], s);
                    unsigned v = ticket_acq_rel(&g_cnt);
                    if (v == NTICKETS - 1) finalize_and_reset(out);
                }
            }
        } else {
            __syncthreads();
            if (wid == 0) {
                s = (l < 8) ? sh[l] : 0.0f;
                #pragma unroll
                for (int off = 4; off; off >>= 1) s += __shfl_down_sync(0xffffffffu, s, off);
                if (l == 0) {
                    atomicAdd(&g_acc[5], s);
                    unsigned v = ticket_acq_rel(&g_cnt);
                    if (v == NTICKETS - 1) finalize_and_reset(out);
                }
            }
        }
    }
    // ---------------- sparse: warp 7 of blocks 0..63, fully independent ----------------
    else {
        const int b    = bid;
        const int lane = tid & 31;

        __shared__ int   s_cell[NBOX], s_anc[NBOX];
        __shared__ float s_tx[NBOX], s_ty[NBOX], s_twx[NBOX], s_twy[NBOX], s_wpos[NBOX];
        int my_key = -1, my_lab = 0;

        if (lane < NBOX) {
            const float* bp = gb + (b * NBOX + lane) * 4;
            float4 bx = *reinterpret_cast<const float4*>(bp);
            int labv = gl[b * NBOX + lane];
            float l = bx.x, t = bx.y, r = bx.z, d = bx.w;
            float cx = (l + r) * 0.5f, cy = (t + d) * 0.5f;
            float w  = r - l,          h  = d - t;

            int bi = 0; float best = -1.0f;
            #pragma unroll
            for (int a = 0; a < NANC; a++) {
                float aw = c_anc[a][0], ah = c_anc[a][1];
                float inter = fminf(w, aw) * fminf(h, ah);
                float un    = w * h + aw * ah - inter;
                float iou   = inter / un;
                if (iou > best) { best = iou; bi = a; }
            }
            int col = (int)floorf(cx * GRIDW); col = min(max(col, 0), GRIDW - 1);
            int row = (int)floorf(cy * GRIDW); row = min(max(row, 0), GRIDW - 1);
            int cell = row * GRIDW + col;

            s_cell[lane] = cell;
            s_anc[lane]  = bi;
            my_key       = cell * NANC + bi;
            my_lab       = labv - 1;
            s_tx[lane]   = cx * GRIDW - (float)col;
            s_ty[lane]   = cy * GRIDW - (float)row;
            s_twx[lane]  = __logf(w / c_anc[bi][0]);
            s_twy[lane]  = __logf(h / c_anc[bi][1]);
            s_wpos[lane] = l;  // replicates reference index bug: gy[...,26] = left coord
        }
        __syncwarp();

        int live = 0, first = 0;
        if (lane < NBOX) {
            live = 1;
            for (int j = lane + 1; j < NBOX; j++)
                if (s_cell[j] * NANC + s_anc[j] == my_key) { live = 0; break; }
            first = 1;
            for (int j = 0; j < lane; j++)
                if (s_cell[j] == s_cell[lane]) { first = 0; break; }
        }
        unsigned mlive  = __ballot_sync(0xffffffffu, live);
        unsigned mfirst = __ballot_sync(0xffffffffu, first);
        int npos   = __popc(mlive);
        int ncellm = __popc(mfirst);
        float nneg = (float)(NANC * NCELL - NANC * ncellm);

        float a_conf = 0.f, a_cls = 0.f, a_txy = 0.f, a_twh = 0.f, a_sub = 0.f;
        const float* base = py + b * CSTRIDE;

        // batch ALL positive gathers (25 loads) before consuming: one memory round
        if (lane < NBOX && live) {
            int cell = s_cell[lane], anc = s_anc[lane], lab = my_lab;
            int o = anc * NCELL + cell;

            float xconf = __ldg(base + o);
            float xc[NCLS];
            #pragma unroll
            for (int f = 0; f < NCLS; f++)
                xc[f] = __ldg(base + o + (f + 1) * (NANC * NCELL));
            float xtx = __ldg(base + o + 21 * (NANC * NCELL));
            float xty = __ldg(base + o + 22 * (NANC * NCELL));
            float xwx = __ldg(base + o + 23 * (NANC * NCELL));
            float xwy = __ldg(base + o + 24 * (NANC * NCELL));

            float p = sigmoid_clip(xconf);
            float om = 1.0f - p;
            a_conf = -0.5f * om * om * __logf(p);

            #pragma unroll
            for (int f = 0; f < NCLS; f++) {
                float pc = sigmoid_clip(xc[f]);
                float g  = (f == lab) ? 1.0f : 0.0f;
                a_cls += -(g * __logf(pc) + (1.0f - g) * __logf(1.0f - pc));
            }

            float wpos = s_wpos[lane];
            float ptx = sigmoid_clip(xtx);
            float pty = sigmoid_clip(xty);
            float gx = s_tx[lane], gy = s_ty[lane];
            float bcex = -(gx * __logf(ptx) + (1.0f - gx) * __logf(1.0f - ptx));
            float bcey = -(gy * __logf(pty) + (1.0f - gy) * __logf(1.0f - pty));
            a_txy = (bcex + bcey) * wpos;

            float dx = xwx - s_twx[lane];
            float dy = xwy - s_twy[lane];
            a_twh = (dx * dx + dy * dy) * wpos;
        }

        // marked-cell anchors: 3 independent gated loads per lane, batched
        {
            float xs[3]; int have[3];
            #pragma unroll
            for (int it = 0; it < 3; it++) {
                int k = lane + it * 32;
                int i = k / NANC, a = k - i * NANC;
                have[it] = (k < NBOX * NANC) && ((mfirst >> i) & 1u);
                if (have[it]) xs[it] = __ldg(base + a * NCELL + s_cell[i]);
            }
            #pragma unroll
            for (int it = 0; it < 3; it++)
                if (have[it]) a_sub += fneg(xs[it]);
        }

        #pragma unroll
        for (int off = 16; off; off >>= 1) {
            a_conf += __shfl_down_sync(0xffffffffu, a_conf, off);
            a_cls  += __shfl_down_sync(0xffffffffu, a_cls,  off);
            a_txy  += __shfl_down_sync(0xffffffffu, a_txy,  off);
            a_twh  += __shfl_down_sync(0xffffffffu, a_twh,  off);
            a_sub  += __shfl_down_sync(0xffffffffu, a_sub,  off);
        }
        if (lane == 0) {
            atomicAdd(&g_acc[0], a_conf);
            atomicAdd(&g_acc[1], a_sub);
            atomicAdd(&g_acc[2], a_cls);
            atomicAdd(&g_acc[3], a_txy);
            atomicAdd(&g_acc[4], a_twh);
            atomicAdd(&g_acc[6], 1.0f / fmaxf((float)npos, EPS16));
            atomicAdd(&g_acc[7], 1.0f / fmaxf(nneg, EPS16));
            atomicAdd(&g_npos, npos);
            unsigned v = ticket_acq_rel(&g_cnt);  // release: covers 8 atomics above
            if (v == NTICKETS - 1) finalize_and_reset(out);
        }
    }
}

extern "C" void kernel_launch(void* const* d_in, const int* in_sizes, int n_in,
                              void* d_out, int out_size) {
    const float* py = (const float*)d_in[0];
    const float* gb = (const float*)d_in[1];
    const int*   gl = (const int*)d_in[2];
    float* out = (float*)d_out;

    k_fused<<<NBLOCKS, NTHREADS>>>(py, gb, gl, out);
}